// round 7
// baseline (speedup 1.0000x reference)
#include <cuda_runtime.h>
#include <cstdint>

// Problem constants (fixed shapes from setup_inputs)
#define N_PTS   20000
#define C_FEAT  64
#define BATCH   2
#define NQ_P    2048
#define NSAMP   32
#define C_OUT   (3 + C_FEAT)          // 67
#define NQ      (BATCH * NQ_P)        // 4096
#define NC      12                    // grid cells per dim, cell = 1/12 >= radius
#define NCELLS  (NC * NC * NC)        // 1728
#define CAND_MAX 128
#define SENT    0x7FFFFFFF

static const float R2F = (float)(0.08 * 0.08);

// -------- scratch (static device globals: allocation-free) --------
// Invariant: g_cell_scr[0..NCELLS) (counts) is ZERO at kernel_launch entry.
// BSS-zeroed at load; scan_kernel re-zeroes after consuming each call.
__device__ int    g_cell_scr[2 * NCELLS];     // [0,NCELLS): counts, [NCELLS,2N): fill cursors
__device__ int    g_cell_start[NCELLS + 1];
__device__ float4 g_sorted[N_PTS];            // (x,y,z, bitcast(orig index))
__device__ float4 g_featT[N_PTS * (C_FEAT / 4)];  // transposed features, (N, C) row-major

__device__ __forceinline__ int cell_of(float v) {
    int c = (int)(v * (float)NC);
    return min(max(c, 0), NC - 1);
}

// exact-match helpers: left-to-right fp32, no FMA contraction
__device__ __forceinline__ float sq3(float a, float b, float c) {
    return __fadd_rn(__fadd_rn(__fmul_rn(a, a), __fmul_rn(b, b)), __fmul_rn(c, c));
}
__device__ __forceinline__ float dot3(float ax, float ay, float az,
                                      float bx, float by, float bz) {
    return __fadd_rn(__fadd_rn(__fmul_rn(ax, bx), __fmul_rn(ay, by)), __fmul_rn(az, bz));
}

// -------- K1: fused transpose (C,N)->(N,C)  +  per-cell count --------
#define T_BLOCKS_X 625                      // ceil(20000/32)
#define T_BLOCKS   (T_BLOCKS_X * 2)         // 2 channel tiles of 32
#define CNT_BLOCKS ((N_PTS + 255) / 256)    // 79

__global__ __launch_bounds__(256) void prep_kernel(const float* __restrict__ feat,
                                                   const float* __restrict__ xyz) {
    int bid = blockIdx.x;
    int tid = threadIdx.x;
    if (bid < T_BLOCKS) {
        // ---- transpose tile ----
        __shared__ float tile[32][33];
        float* featT = (float*)g_featT;
        int bx = bid % T_BLOCKS_X, by = bid / T_BLOCKS_X;
        int tx = tid & 31, ty = tid >> 5;           // 32 x 8
        int n  = bx * 32 + tx;
        int c0 = by * 32 + ty;
        #pragma unroll
        for (int k = 0; k < 32; k += 8) {
            int c = c0 + k;
            if (n < N_PTS && c < C_FEAT)
                tile[ty + k][tx] = feat[(size_t)c * N_PTS + n];
        }
        __syncthreads();
        int c2 = by * 32 + tx;
        int n2 = bx * 32 + ty;
        #pragma unroll
        for (int k = 0; k < 32; k += 8) {
            int n3 = n2 + k;
            if (n3 < N_PTS && c2 < C_FEAT)
                featT[(size_t)n3 * C_FEAT + c2] = tile[tx][ty + k];
        }
    } else {
        // ---- count points per cell ----
        int n = (bid - T_BLOCKS) * 256 + tid;
        if (n >= N_PTS) return;
        float x = xyz[3 * n], y = xyz[3 * n + 1], z = xyz[3 * n + 2];
        int cell = (cell_of(z) * NC + cell_of(y)) * NC + cell_of(x);
        atomicAdd(&g_cell_scr[cell], 1);
    }
}

// -------- K2: warp-shuffle exclusive scan (1 block, 1024 thr, 2 cells/thr) ----
// Also zeroes counts (next replay) and scatter cursors (this replay).
__global__ __launch_bounds__(1024) void scan_kernel() {
    __shared__ int wtot[32];
    __shared__ int woff[32];
    int t    = threadIdx.x;
    int lane = t & 31;
    int wid  = t >> 5;
    int i0 = 2 * t, i1 = 2 * t + 1;

    int c0 = (i0 < NCELLS) ? g_cell_scr[i0] : 0;
    int c1 = (i1 < NCELLS) ? g_cell_scr[i1] : 0;
    int s  = c0 + c1;

    int incl = s;
    #pragma unroll
    for (int o = 1; o < 32; o <<= 1) {
        int nb = __shfl_up_sync(0xffffffffu, incl, o);
        if (lane >= o) incl += nb;
    }
    if (lane == 31) wtot[wid] = incl;
    __syncthreads();
    if (wid == 0) {
        int v = wtot[lane];
        int iv = v;
        #pragma unroll
        for (int o = 1; o < 32; o <<= 1) {
            int nb = __shfl_up_sync(0xffffffffu, iv, o);
            if (lane >= o) iv += nb;
        }
        woff[lane] = iv - v;
    }
    __syncthreads();

    int ex = woff[wid] + incl - s;
    if (i0 < NCELLS) g_cell_start[i0] = ex;
    if (i1 < NCELLS) g_cell_start[i1] = ex + c0;
    if (i1 == NCELLS - 1) g_cell_start[NCELLS] = ex + c0 + c1;

    if (i0 < NCELLS) { g_cell_scr[i0] = 0; g_cell_scr[NCELLS + i0] = 0; }
    if (i1 < NCELLS) { g_cell_scr[i1] = 0; g_cell_scr[NCELLS + i1] = 0; }
}

// -------- K3: scatter points into sorted-by-cell order --------
__global__ __launch_bounds__(256) void scatter_kernel(const float* __restrict__ xyz) {
    int n = blockIdx.x * blockDim.x + threadIdx.x;
    if (n >= N_PTS) return;
    float x = xyz[3 * n], y = xyz[3 * n + 1], z = xyz[3 * n + 2];
    int cell = (cell_of(z) * NC + cell_of(y)) * NC + cell_of(x);
    int pos = g_cell_start[cell] + atomicAdd(&g_cell_scr[NCELLS + cell], 1);
    g_sorted[pos] = make_float4(x, y, z, __int_as_float(n));
}

// -------- K4: ball query (grid) + group, one warp per query, 8 warps/block ---
#define WPB 8
#define FULLM 0xffffffffu

__global__ __launch_bounds__(WPB * 32, 4) void query_group_kernel(
    const float* __restrict__ new_xyz,
    const float* __restrict__ xyz,
    float* __restrict__ out,
    int write_idn)
{
    __shared__ __align__(16) int cand[WPB][CAND_MAX];  // candidates -> sorted ids
    __shared__ float4 sbuf[WPB][NSAMP * 4];            // 2KB/warp chunked staging
    int w    = threadIdx.x >> 5;
    int lane = threadIdx.x & 31;
    int q = blockIdx.x * WPB + w;
    if (q >= NQ) return;
    int b = q >> 11;            // NQ_P == 2048
    int p = q & (NQ_P - 1);

    float qx = new_xyz[3 * q], qy = new_xyz[3 * q + 1], qz = new_xyz[3 * q + 2];
    float q2 = sq3(qx, qy, qz);
    const float R2 = R2F;
    const float rp = 0.0801f;   // padded radius for cell coverage

    int x0 = max(0,      (int)floorf((qx - rp) * (float)NC));
    int x1 = min(NC - 1, (int)floorf((qx + rp) * (float)NC));
    int y0 = max(0,      (int)floorf((qy - rp) * (float)NC));
    int y1 = min(NC - 1, (int)floorf((qy + rp) * (float)NC));
    int z0 = max(0,      (int)floorf((qz - rp) * (float)NC));
    int z1 = min(NC - 1, (int)floorf((qz + rp) * (float)NC));

    // ---- prefetch all row ranges in parallel across lanes ----
    int ny    = y1 - y0 + 1;                 // <= 3
    int nrows = ny * (z1 - z0 + 1);          // <= 9
    int rs0 = 0, rs1 = 0;
    if (lane < nrows) {
        int rz = lane / ny;
        int cy = y0 + (lane - rz * ny);
        int crow = ((z0 + rz) * NC + cy) * NC;
        rs0 = g_cell_start[crow + x0];
        rs1 = g_cell_start[crow + x1 + 1];
    }

    // ---- candidate scan: collect in-ball original indices ----
    int base = 0;
    for (int r = 0; r < nrows; r++) {
        int s0 = __shfl_sync(FULLM, rs0, r);
        int s1 = __shfl_sync(FULLM, rs1, r);
        for (int j0 = s0; j0 < s1; j0 += 32) {
            int j = j0 + lane;
            bool inb = false; int pid = 0;
            if (j < s1) {
                float4 pt = g_sorted[j];
                float x2  = sq3(pt.x, pt.y, pt.z);
                float dt  = dot3(qx, qy, qz, pt.x, pt.y, pt.z);
                float d2  = __fsub_rn(__fadd_rn(q2, x2), __fmul_rn(2.0f, dt));
                inb = d2 < R2;
                pid = __float_as_int(pt.w);
            }
            unsigned m = __ballot_sync(FULLM, inb);
            if (inb) {
                int pos = base + __popc(m & ((1u << lane) - 1u));
                if (pos < CAND_MAX) cand[w][pos] = pid;
            }
            base += __popc(m);
        }
    }
    int M = min(base, CAND_MAX);
    // pad to multiple of 4 with SENT for int4 rank scan
    if (lane < 3 && M + lane < CAND_MAX) cand[w][M + lane] = SENT;
    __syncwarp();

    // ---- rank-based selection: lane owns candidates lane, lane+32, ... ----
    int v0 = (lane      < M) ? cand[w][lane]      : SENT;
    int v1 = (lane + 32 < M) ? cand[w][lane + 32] : SENT;
    int v2 = (lane + 64 < M) ? cand[w][lane + 64] : SENT;
    int v3 = (lane + 96 < M) ? cand[w][lane + 96] : SENT;

    int r0 = 0, r1 = 0, r2 = 0, r3 = 0;
    {
        const int4* cp4 = reinterpret_cast<const int4*>(cand[w]);
        int nj4 = (M + 3) >> 2;
        if (M <= 64) {
            for (int j4 = 0; j4 < nj4; j4++) {
                int4 s = cp4[j4];
                r0 += (s.x < v0) + (s.y < v0) + (s.z < v0) + (s.w < v0);
                r1 += (s.x < v1) + (s.y < v1) + (s.z < v1) + (s.w < v1);
            }
        } else {
            for (int j4 = 0; j4 < nj4; j4++) {
                int4 s = cp4[j4];
                r0 += (s.x < v0) + (s.y < v0) + (s.z < v0) + (s.w < v0);
                r1 += (s.x < v1) + (s.y < v1) + (s.z < v1) + (s.w < v1);
                r2 += (s.x < v2) + (s.y < v2) + (s.z < v2) + (s.w < v2);
                r3 += (s.x < v3) + (s.y < v3) + (s.z < v3) + (s.w < v3);
            }
        }
    }
    __syncwarp();   // all reads of cand done before overwrite
    // scatter: sorted ascending, slot = rank (indices unique -> ranks unique).
    // SENT entries MUST NOT scatter (fast path leaves their rank at 0!).
    if (v0 != SENT && r0 < NSAMP) cand[w][r0] = v0;
    if (v1 != SENT && r1 < NSAMP) cand[w][r1] = v1;
    if (v2 != SENT && r2 < NSAMP) cand[w][r2] = v2;
    if (v3 != SENT && r3 < NSAMP) cand[w][r3] = v3;
    __syncwarp();

    int cnt   = min(M, NSAMP);
    bool valid = lane < cnt;
    int first = (cnt > 0) ? cand[w][0] : 0;
    int id    = valid ? cand[w][lane] : first;
    float idn = (valid || cnt == 0) ? 1.0f : 0.0f;

    // ---- xyz part (3 channels), lane = sample slot ----
    float px = xyz[3 * id], py = xyz[3 * id + 1], pz = xyz[3 * id + 2];
    size_t ob = (((size_t)b * C_OUT) * NQ_P + (size_t)p) * NSAMP + (size_t)lane;
    const size_t st = (size_t)NQ_P * NSAMP;
    out[ob]          = __fsub_rn(px, qx);
    out[ob + st]     = __fsub_rn(py, qy);
    out[ob + 2 * st] = __fsub_rn(pz, qz);

    // ---- cooperative feature gather, chunked smem staging (2KB/warp) ----
    float4* mybuf = sbuf[w];
    size_t o = ob + 3 * st;
    int lc = lane & 3;                 // chunk index within pass
    int lr = lane >> 2;                // row group base
    int myswz = (lane & 3) ^ ((lane >> 2) & 3);   // read swizzle base for row=lane
    #pragma unroll
    for (int kk = 0; kk < 4; kk++) {
        // stage chunks [4kk, 4kk+4) of all 32 sample rows
        #pragma unroll
        for (int t = 0; t < 4; t++) {
            int r = lr + 8 * t;
            int id_r = __shfl_sync(FULLM, id, r);
            float4 val = g_featT[(size_t)id_r * 16 + 4 * kk + lc];
            mybuf[r * 4 + (lc ^ (r & 3) ^ ((r >> 2) & 3))] = val;
        }
        __syncwarp();
        // read own row transposed, write 16 channels
        #pragma unroll
        for (int j = 0; j < 4; j++) {
            float4 f = mybuf[lane * 4 + (j ^ myswz)];
            size_t oo = o + (size_t)(4 * (4 * kk + j)) * st;
            out[oo]          = f.x;
            out[oo + st]     = f.y;
            out[oo + 2 * st] = f.z;
            out[oo + 3 * st] = f.w;
        }
        __syncwarp();   // protect buffer before next pass overwrites
    }

    if (write_idn) {
        size_t nfe = (size_t)BATCH * C_OUT * NQ_P * NSAMP;
        out[nfe + (size_t)q * NSAMP + lane] = idn;
    }
}

extern "C" void kernel_launch(void* const* d_in, const int* in_sizes, int n_in,
                              void* d_out, int out_size) {
    const float* xyz     = (const float*)d_in[0];   // (20000, 3)
    const float* new_xyz = (const float*)d_in[1];   // (2, 2048, 3)
    const float* feat    = (const float*)d_in[2];   // (64, 20000)
    float* out = (float*)d_out;

    long long nfe = (long long)BATCH * C_OUT * NQ_P * NSAMP;           // 18,350,080
    int write_idn = ((long long)out_size >= nfe + (long long)NQ * NSAMP) ? 1 : 0;

    prep_kernel<<<T_BLOCKS + CNT_BLOCKS, 256>>>(feat, xyz);   // transpose + count (fused)
    scan_kernel<<<1, 1024>>>();                               // scan + re-zero scratch
    scatter_kernel<<<CNT_BLOCKS, 256>>>(xyz);
    query_group_kernel<<<NQ / WPB, WPB * 32>>>(new_xyz, xyz, out, write_idn);
}

// round 8
// speedup vs baseline: 1.0016x; 1.0016x over previous
#include <cuda_runtime.h>
#include <cstdint>

// Problem constants (fixed shapes from setup_inputs)
#define N_PTS   20000
#define C_FEAT  64
#define BATCH   2
#define NQ_P    2048
#define NSAMP   32
#define C_OUT   (3 + C_FEAT)          // 67
#define NQ      (BATCH * NQ_P)        // 4096
#define NC      12                    // grid cells per dim, cell = 1/12 >= radius
#define NCELLS  (NC * NC * NC)        // 1728
#define CAND_MAX 128
#define SENT    0x7FFFFFFF
#define FULLM 0xffffffffu

static const float R2F = (float)(0.08 * 0.08);

// -------- scratch (static device globals: allocation-free) --------
// Invariant: g_cell_cnt[0..NCELLS) is ZERO at kernel_launch entry.
// BSS-zeroed at load; build_kernel re-zeroes after consuming each call.
__device__ int    g_cell_cnt[NCELLS];
__device__ int    g_cell_start[NCELLS + 1];
__device__ float4 g_sorted[N_PTS];            // (x,y,z, bitcast(orig index))
__device__ float4 g_featT[N_PTS * (C_FEAT / 4)];  // transposed features, (N, C) row-major
__device__ int    g_idx[NQ * NSAMP];          // selected (padded) sample ids

__device__ __forceinline__ int cell_of(float v) {
    int c = (int)(v * (float)NC);
    return min(max(c, 0), NC - 1);
}

// exact-match helpers: left-to-right fp32, no FMA contraction
__device__ __forceinline__ float sq3(float a, float b, float c) {
    return __fadd_rn(__fadd_rn(__fmul_rn(a, a), __fmul_rn(b, b)), __fmul_rn(c, c));
}
__device__ __forceinline__ float dot3(float ax, float ay, float az,
                                      float bx, float by, float bz) {
    return __fadd_rn(__fadd_rn(__fmul_rn(ax, bx), __fmul_rn(ay, by)), __fmul_rn(az, bz));
}

// -------- K1: fused transpose (C,N)->(N,C)  +  per-cell count --------
#define T_BLOCKS_X 625                      // ceil(20000/32)
#define T_BLOCKS   (T_BLOCKS_X * 2)         // 2 channel tiles of 32
#define CNT_BLOCKS ((N_PTS + 255) / 256)    // 79

__global__ __launch_bounds__(256) void prep_kernel(const float* __restrict__ feat,
                                                   const float* __restrict__ xyz) {
    int bid = blockIdx.x;
    int tid = threadIdx.x;
    if (bid < T_BLOCKS) {
        // ---- transpose tile ----
        __shared__ float tile[32][33];
        float* featT = (float*)g_featT;
        int bx = bid % T_BLOCKS_X, by = bid / T_BLOCKS_X;
        int tx = tid & 31, ty = tid >> 5;           // 32 x 8
        int n  = bx * 32 + tx;
        int c0 = by * 32 + ty;
        #pragma unroll
        for (int k = 0; k < 32; k += 8) {
            int c = c0 + k;
            if (n < N_PTS && c < C_FEAT)
                tile[ty + k][tx] = feat[(size_t)c * N_PTS + n];
        }
        __syncthreads();
        int c2 = by * 32 + tx;
        int n2 = bx * 32 + ty;
        #pragma unroll
        for (int k = 0; k < 32; k += 8) {
            int n3 = n2 + k;
            if (n3 < N_PTS && c2 < C_FEAT)
                featT[(size_t)n3 * C_FEAT + c2] = tile[tx][ty + k];
        }
    } else {
        // ---- count points per cell ----
        int n = (bid - T_BLOCKS) * 256 + tid;
        if (n >= N_PTS) return;
        float x = xyz[3 * n], y = xyz[3 * n + 1], z = xyz[3 * n + 2];
        int cell = (cell_of(z) * NC + cell_of(y)) * NC + cell_of(x);
        atomicAdd(&g_cell_cnt[cell], 1);
    }
}

// -------- K2: fused scan + scatter (single block, smem-resident grid) --------
// Scans counts -> cell starts (also published to g_cell_start for K3), then
// scatters all points into cell-sorted order using smem cursors.
// Re-zeroes g_cell_cnt to restore the entry invariant for the next replay.
__global__ __launch_bounds__(1024) void build_kernel(const float* __restrict__ xyz) {
    __shared__ int s_start[NCELLS];
    __shared__ int s_cur[NCELLS];
    __shared__ int wtot[32], woff[32];
    int t    = threadIdx.x;
    int lane = t & 31;
    int wid  = t >> 5;
    int i0 = 2 * t, i1 = 2 * t + 1;

    int c0 = (i0 < NCELLS) ? g_cell_cnt[i0] : 0;
    int c1 = (i1 < NCELLS) ? g_cell_cnt[i1] : 0;
    int s  = c0 + c1;

    int incl = s;
    #pragma unroll
    for (int o = 1; o < 32; o <<= 1) {
        int nb = __shfl_up_sync(FULLM, incl, o);
        if (lane >= o) incl += nb;
    }
    if (lane == 31) wtot[wid] = incl;
    __syncthreads();
    if (wid == 0) {
        int v = wtot[lane];
        int iv = v;
        #pragma unroll
        for (int o = 1; o < 32; o <<= 1) {
            int nb = __shfl_up_sync(FULLM, iv, o);
            if (lane >= o) iv += nb;
        }
        woff[lane] = iv - v;
    }
    __syncthreads();

    int ex = woff[wid] + incl - s;
    if (i0 < NCELLS) {
        g_cell_start[i0] = ex;  s_start[i0] = ex;  s_cur[i0] = 0;  g_cell_cnt[i0] = 0;
    }
    if (i1 < NCELLS) {
        g_cell_start[i1] = ex + c0;  s_start[i1] = ex + c0;  s_cur[i1] = 0;  g_cell_cnt[i1] = 0;
    }
    if (i1 == NCELLS - 1) g_cell_start[NCELLS] = ex + c0 + c1;
    __syncthreads();

    for (int n = t; n < N_PTS; n += 1024) {
        float x = xyz[3 * n], y = xyz[3 * n + 1], z = xyz[3 * n + 2];
        int cell = (cell_of(z) * NC + cell_of(y)) * NC + cell_of(x);
        int pos = s_start[cell] + atomicAdd(&s_cur[cell], 1);
        g_sorted[pos] = make_float4(x, y, z, __int_as_float(n));
    }
}

// -------- K3: ball query (grid) + select + xyz channels, one warp/query -----
#define WPB 8
__global__ __launch_bounds__(WPB * 32) void query_kernel(
    const float* __restrict__ new_xyz,
    const float* __restrict__ xyz,
    float* __restrict__ out,
    int write_idn)
{
    __shared__ __align__(16) int cand[WPB][CAND_MAX];  // candidates -> sorted ids
    int w    = threadIdx.x >> 5;
    int lane = threadIdx.x & 31;
    int q = blockIdx.x * WPB + w;
    int b = q >> 11;            // NQ_P == 2048
    int p = q & (NQ_P - 1);

    float qx = new_xyz[3 * q], qy = new_xyz[3 * q + 1], qz = new_xyz[3 * q + 2];
    float q2 = sq3(qx, qy, qz);
    const float R2 = R2F;
    const float rp = 0.0801f;   // padded radius for cell coverage

    int x0 = max(0,      (int)floorf((qx - rp) * (float)NC));
    int x1 = min(NC - 1, (int)floorf((qx + rp) * (float)NC));
    int y0 = max(0,      (int)floorf((qy - rp) * (float)NC));
    int y1 = min(NC - 1, (int)floorf((qy + rp) * (float)NC));
    int z0 = max(0,      (int)floorf((qz - rp) * (float)NC));
    int z1 = min(NC - 1, (int)floorf((qz + rp) * (float)NC));

    // ---- prefetch all row ranges in parallel across lanes ----
    int ny    = y1 - y0 + 1;                 // <= 3
    int nrows = ny * (z1 - z0 + 1);          // <= 9
    int rs0 = 0, rs1 = 0;
    if (lane < nrows) {
        int rz = lane / ny;
        int cy = y0 + (lane - rz * ny);
        int crow = ((z0 + rz) * NC + cy) * NC;
        rs0 = g_cell_start[crow + x0];
        rs1 = g_cell_start[crow + x1 + 1];
    }

    // ---- candidate scan: collect in-ball original indices ----
    int base = 0;
    for (int r = 0; r < nrows; r++) {
        int s0 = __shfl_sync(FULLM, rs0, r);
        int s1 = __shfl_sync(FULLM, rs1, r);
        for (int j0 = s0; j0 < s1; j0 += 32) {
            int j = j0 + lane;
            bool inb = false; int pid = 0;
            if (j < s1) {
                float4 pt = g_sorted[j];
                float x2  = sq3(pt.x, pt.y, pt.z);
                float dt  = dot3(qx, qy, qz, pt.x, pt.y, pt.z);
                float d2  = __fsub_rn(__fadd_rn(q2, x2), __fmul_rn(2.0f, dt));
                inb = d2 < R2;
                pid = __float_as_int(pt.w);
            }
            unsigned m = __ballot_sync(FULLM, inb);
            if (inb) {
                int pos = base + __popc(m & ((1u << lane) - 1u));
                if (pos < CAND_MAX) cand[w][pos] = pid;
            }
            base += __popc(m);
        }
    }
    int M = min(base, CAND_MAX);
    // pad to multiple of 4 with SENT for int4 rank scan
    if (lane < 3 && M + lane < CAND_MAX) cand[w][M + lane] = SENT;
    __syncwarp();

    // ---- rank-based selection: lane owns candidates lane, lane+32, ... ----
    int v0 = (lane      < M) ? cand[w][lane]      : SENT;
    int v1 = (lane + 32 < M) ? cand[w][lane + 32] : SENT;
    int v2 = (lane + 64 < M) ? cand[w][lane + 64] : SENT;
    int v3 = (lane + 96 < M) ? cand[w][lane + 96] : SENT;

    int r0 = 0, r1 = 0, r2 = 0, r3 = 0;
    {
        const int4* cp4 = reinterpret_cast<const int4*>(cand[w]);
        int nj4 = (M + 3) >> 2;
        if (M <= 64) {
            for (int j4 = 0; j4 < nj4; j4++) {
                int4 sv = cp4[j4];
                r0 += (sv.x < v0) + (sv.y < v0) + (sv.z < v0) + (sv.w < v0);
                r1 += (sv.x < v1) + (sv.y < v1) + (sv.z < v1) + (sv.w < v1);
            }
        } else {
            for (int j4 = 0; j4 < nj4; j4++) {
                int4 sv = cp4[j4];
                r0 += (sv.x < v0) + (sv.y < v0) + (sv.z < v0) + (sv.w < v0);
                r1 += (sv.x < v1) + (sv.y < v1) + (sv.z < v1) + (sv.w < v1);
                r2 += (sv.x < v2) + (sv.y < v2) + (sv.z < v2) + (sv.w < v2);
                r3 += (sv.x < v3) + (sv.y < v3) + (sv.z < v3) + (sv.w < v3);
            }
        }
    }
    __syncwarp();   // all reads of cand done before overwrite
    // scatter: sorted ascending, slot = rank (indices unique -> ranks unique).
    // SENT entries MUST NOT scatter (fast path leaves their rank at 0).
    if (v0 != SENT && r0 < NSAMP) cand[w][r0] = v0;
    if (v1 != SENT && r1 < NSAMP) cand[w][r1] = v1;
    if (v2 != SENT && r2 < NSAMP) cand[w][r2] = v2;
    if (v3 != SENT && r3 < NSAMP) cand[w][r3] = v3;
    __syncwarp();

    int cnt   = min(M, NSAMP);
    bool valid = lane < cnt;
    int first = (cnt > 0) ? cand[w][0] : 0;
    int id    = valid ? cand[w][lane] : first;
    float idn = (valid || cnt == 0) ? 1.0f : 0.0f;

    g_idx[q * NSAMP + lane] = id;             // coalesced, consumed by K4

    // ---- xyz part (3 channels), lane = sample slot ----
    float px = xyz[3 * id], py = xyz[3 * id + 1], pz = xyz[3 * id + 2];
    size_t ob = (((size_t)b * C_OUT) * NQ_P + (size_t)p) * NSAMP + (size_t)lane;
    const size_t st = (size_t)NQ_P * NSAMP;
    out[ob]          = __fsub_rn(px, qx);
    out[ob + st]     = __fsub_rn(py, qy);
    out[ob + 2 * st] = __fsub_rn(pz, qz);

    if (write_idn) {
        size_t nfe = (size_t)BATCH * C_OUT * NQ_P * NSAMP;
        out[nfe + (size_t)q * NSAMP + lane] = idn;
    }
}

// -------- K4: feature grouping, 4 warps per query (one per channel-quad) ----
// Massive parallelism (16384 warps) hides all gather latency; smem transpose
// staging keeps both gather loads and output stores coalesced.
#define GW_PB 8     // warps per block
__global__ __launch_bounds__(GW_PB * 32) void group_kernel(float* __restrict__ out) {
    __shared__ float4 sbuf[GW_PB][NSAMP * 4];      // 2KB per warp
    int w    = threadIdx.x >> 5;
    int lane = threadIdx.x & 31;
    int gw = blockIdx.x * GW_PB + w;
    int q  = gw >> 2;          // query
    int kk = gw & 3;           // channel-quad group: chunks [4kk, 4kk+4)
    int b = q >> 11;
    int p = q & (NQ_P - 1);

    int id = g_idx[q * NSAMP + lane];              // coalesced

    float4* mybuf = sbuf[w];
    int lc = lane & 3;                 // chunk within group
    int lr = lane >> 2;                // row base
    // stage chunks [4kk, 4kk+4) of all 32 sample rows (coalesced-ish loads)
    #pragma unroll
    for (int t = 0; t < 4; t++) {
        int r = lr + 8 * t;
        int id_r = __shfl_sync(FULLM, id, r);
        float4 val = g_featT[(size_t)id_r * 16 + 4 * kk + lc];
        mybuf[r * 4 + (lc ^ (r & 3) ^ ((r >> 2) & 3))] = val;
    }
    __syncwarp();

    // drain transposed: lane = sample, 16 channels -> 16 coalesced stores
    size_t ob = (((size_t)b * C_OUT) * NQ_P + (size_t)p) * NSAMP + (size_t)lane;
    const size_t st = (size_t)NQ_P * NSAMP;
    size_t o = ob + 3 * st;
    int myswz = (lane & 3) ^ ((lane >> 2) & 3);
    #pragma unroll
    for (int j = 0; j < 4; j++) {
        float4 f = mybuf[lane * 4 + (j ^ myswz)];
        size_t oo = o + (size_t)(4 * (4 * kk + j)) * st;
        out[oo]          = f.x;
        out[oo + st]     = f.y;
        out[oo + 2 * st] = f.z;
        out[oo + 3 * st] = f.w;
    }
}

extern "C" void kernel_launch(void* const* d_in, const int* in_sizes, int n_in,
                              void* d_out, int out_size) {
    const float* xyz     = (const float*)d_in[0];   // (20000, 3)
    const float* new_xyz = (const float*)d_in[1];   // (2, 2048, 3)
    const float* feat    = (const float*)d_in[2];   // (64, 20000)
    float* out = (float*)d_out;

    long long nfe = (long long)BATCH * C_OUT * NQ_P * NSAMP;           // 18,350,080
    int write_idn = ((long long)out_size >= nfe + (long long)NQ * NSAMP) ? 1 : 0;

    prep_kernel<<<T_BLOCKS + CNT_BLOCKS, 256>>>(feat, xyz);   // transpose + count
    build_kernel<<<1, 1024>>>(xyz);                           // scan + scatter (fused)
    query_kernel<<<NQ / WPB, WPB * 32>>>(new_xyz, xyz, out, write_idn);
    group_kernel<<<(NQ * 4) / GW_PB, GW_PB * 32>>>(out);
}

// round 10
// speedup vs baseline: 1.1644x; 1.1625x over previous
#include <cuda_runtime.h>
#include <cstdint>

// Problem constants (fixed shapes from setup_inputs)
#define N_PTS   20000
#define C_FEAT  64
#define BATCH   2
#define NQ_P    2048
#define NSAMP   32
#define C_OUT   (3 + C_FEAT)          // 67
#define NQ      (BATCH * NQ_P)        // 4096
#define NC      12                    // grid cells per dim, cell = 1/12 >= radius
#define NCELLS  (NC * NC * NC)        // 1728
#define CAND_MAX 128
#define SENT    0x7FFFFFFF
#define FULLM 0xffffffffu

static const float R2F = (float)(0.08 * 0.08);

// -------- scratch (static device globals: allocation-free) --------
// Invariant: g_cell_scr[0..NCELLS) (counts) is ZERO at kernel_launch entry.
// BSS-zeroed at load; scan_kernel re-zeroes after consuming each call.
__device__ int    g_cell_scr[2 * NCELLS];     // [0,NCELLS): counts, [NCELLS,2N): cursors
__device__ int    g_cell_start[NCELLS + 1];
__device__ float4 g_sorted[N_PTS];            // (x,y,z, bitcast(orig index))
__device__ float4 g_featT[N_PTS * (C_FEAT / 4)];  // transposed features, (N, C) row-major
__device__ int    g_idx[NQ * NSAMP];          // selected (padded) sample ids

__device__ __forceinline__ int cell_of(float v) {
    int c = (int)(v * (float)NC);
    return min(max(c, 0), NC - 1);
}

// exact-match helpers: left-to-right fp32, no FMA contraction
__device__ __forceinline__ float sq3(float a, float b, float c) {
    return __fadd_rn(__fadd_rn(__fmul_rn(a, a), __fmul_rn(b, b)), __fmul_rn(c, c));
}
__device__ __forceinline__ float dot3(float ax, float ay, float az,
                                      float bx, float by, float bz) {
    return __fadd_rn(__fadd_rn(__fmul_rn(ax, bx), __fmul_rn(ay, by)), __fmul_rn(az, bz));
}

// -------- KA (side stream): transpose features (C,N) -> (N,C) --------
#define T_BLOCKS_X 625                      // ceil(20000/32)
#define T_BLOCKS   (T_BLOCKS_X * 2)         // 2 channel tiles of 32
#define CNT_BLOCKS ((N_PTS + 255) / 256)    // 79

__global__ __launch_bounds__(256) void transpose_kernel(const float* __restrict__ feat) {
    __shared__ float tile[32][33];
    float* featT = (float*)g_featT;
    int bid = blockIdx.x;
    int bx = bid % T_BLOCKS_X, by = bid / T_BLOCKS_X;
    int tx = threadIdx.x & 31, ty = threadIdx.x >> 5;   // 32 x 8
    int n  = bx * 32 + tx;
    int c0 = by * 32 + ty;
    #pragma unroll
    for (int k = 0; k < 32; k += 8) {
        int c = c0 + k;
        if (n < N_PTS && c < C_FEAT)
            tile[ty + k][tx] = feat[(size_t)c * N_PTS + n];
    }
    __syncthreads();
    int c2 = by * 32 + tx;
    int n2 = bx * 32 + ty;
    #pragma unroll
    for (int k = 0; k < 32; k += 8) {
        int n3 = n2 + k;
        if (n3 < N_PTS && c2 < C_FEAT)
            featT[(size_t)n3 * C_FEAT + c2] = tile[tx][ty + k];
    }
}

// -------- K1: count points per cell --------
__global__ __launch_bounds__(256) void count_kernel(const float* __restrict__ xyz) {
    int n = blockIdx.x * blockDim.x + threadIdx.x;
    if (n >= N_PTS) return;
    float x = xyz[3 * n], y = xyz[3 * n + 1], z = xyz[3 * n + 2];
    int cell = (cell_of(z) * NC + cell_of(y)) * NC + cell_of(x);
    atomicAdd(&g_cell_scr[cell], 1);
}

// -------- K2: warp-shuffle exclusive scan (1 block, 2 cells/thread) ----------
// Also zeroes counts (next replay) and scatter cursors (this replay).
__global__ __launch_bounds__(1024) void scan_kernel() {
    __shared__ int wtot[32], woff[32];
    int t    = threadIdx.x;
    int lane = t & 31;
    int wid  = t >> 5;
    int i0 = 2 * t, i1 = 2 * t + 1;

    int c0 = (i0 < NCELLS) ? g_cell_scr[i0] : 0;
    int c1 = (i1 < NCELLS) ? g_cell_scr[i1] : 0;
    int s  = c0 + c1;

    int incl = s;
    #pragma unroll
    for (int o = 1; o < 32; o <<= 1) {
        int nb = __shfl_up_sync(FULLM, incl, o);
        if (lane >= o) incl += nb;
    }
    if (lane == 31) wtot[wid] = incl;
    __syncthreads();
    if (wid == 0) {
        int v = wtot[lane];
        int iv = v;
        #pragma unroll
        for (int o = 1; o < 32; o <<= 1) {
            int nb = __shfl_up_sync(FULLM, iv, o);
            if (lane >= o) iv += nb;
        }
        woff[lane] = iv - v;
    }
    __syncthreads();

    int ex = woff[wid] + incl - s;
    if (i0 < NCELLS) g_cell_start[i0] = ex;
    if (i1 < NCELLS) g_cell_start[i1] = ex + c0;
    if (i1 == NCELLS - 1) g_cell_start[NCELLS] = ex + c0 + c1;

    if (i0 < NCELLS) { g_cell_scr[i0] = 0; g_cell_scr[NCELLS + i0] = 0; }
    if (i1 < NCELLS) { g_cell_scr[i1] = 0; g_cell_scr[NCELLS + i1] = 0; }
}

// -------- K3: scatter points into sorted-by-cell order (full grid) ----------
__global__ __launch_bounds__(256) void scatter_kernel(const float* __restrict__ xyz) {
    int n = blockIdx.x * blockDim.x + threadIdx.x;
    if (n >= N_PTS) return;
    float x = xyz[3 * n], y = xyz[3 * n + 1], z = xyz[3 * n + 2];
    int cell = (cell_of(z) * NC + cell_of(y)) * NC + cell_of(x);
    int pos = g_cell_start[cell] + atomicAdd(&g_cell_scr[NCELLS + cell], 1);
    g_sorted[pos] = make_float4(x, y, z, __int_as_float(n));
}

// -------- K4: ball query (grid) + select + xyz channels, one warp/query -----
#define WPB 8
__global__ __launch_bounds__(WPB * 32) void query_kernel(
    const float* __restrict__ new_xyz,
    const float* __restrict__ xyz,
    float* __restrict__ out,
    int write_idn)
{
    __shared__ __align__(16) int cand[WPB][CAND_MAX];  // candidates -> sorted ids
    int w    = threadIdx.x >> 5;
    int lane = threadIdx.x & 31;
    int q = blockIdx.x * WPB + w;
    int b = q >> 11;            // NQ_P == 2048
    int p = q & (NQ_P - 1);

    float qx = new_xyz[3 * q], qy = new_xyz[3 * q + 1], qz = new_xyz[3 * q + 2];
    float q2 = sq3(qx, qy, qz);
    const float R2 = R2F;
    const float rp = 0.0801f;   // padded radius for cell coverage

    int x0 = max(0,      (int)floorf((qx - rp) * (float)NC));
    int x1 = min(NC - 1, (int)floorf((qx + rp) * (float)NC));
    int y0 = max(0,      (int)floorf((qy - rp) * (float)NC));
    int y1 = min(NC - 1, (int)floorf((qy + rp) * (float)NC));
    int z0 = max(0,      (int)floorf((qz - rp) * (float)NC));
    int z1 = min(NC - 1, (int)floorf((qz + rp) * (float)NC));

    // ---- prefetch all row ranges in parallel across lanes ----
    int ny    = y1 - y0 + 1;                 // <= 3
    int nrows = ny * (z1 - z0 + 1);          // <= 9
    int rs0 = 0, rs1 = 0;
    if (lane < nrows) {
        int rz = lane / ny;
        int cy = y0 + (lane - rz * ny);
        int crow = ((z0 + rz) * NC + cy) * NC;
        rs0 = g_cell_start[crow + x0];
        rs1 = g_cell_start[crow + x1 + 1];
    }

    // ---- candidate scan: collect in-ball original indices ----
    int base = 0;
    for (int r = 0; r < nrows; r++) {
        int s0 = __shfl_sync(FULLM, rs0, r);
        int s1 = __shfl_sync(FULLM, rs1, r);
        for (int j0 = s0; j0 < s1; j0 += 32) {
            int j = j0 + lane;
            bool inb = false; int pid = 0;
            if (j < s1) {
                float4 pt = g_sorted[j];
                float x2  = sq3(pt.x, pt.y, pt.z);
                float dt  = dot3(qx, qy, qz, pt.x, pt.y, pt.z);
                float d2  = __fsub_rn(__fadd_rn(q2, x2), __fmul_rn(2.0f, dt));
                inb = d2 < R2;
                pid = __float_as_int(pt.w);
            }
            unsigned m = __ballot_sync(FULLM, inb);
            if (inb) {
                int pos = base + __popc(m & ((1u << lane) - 1u));
                if (pos < CAND_MAX) cand[w][pos] = pid;
            }
            base += __popc(m);
        }
    }
    int M = min(base, CAND_MAX);
    // pad to multiple of 4 with SENT for int4 rank scan
    if (lane < 3 && M + lane < CAND_MAX) cand[w][M + lane] = SENT;
    __syncwarp();

    // ---- rank-based selection: lane owns candidates lane, lane+32, ... ----
    int v0 = (lane      < M) ? cand[w][lane]      : SENT;
    int v1 = (lane + 32 < M) ? cand[w][lane + 32] : SENT;
    int v2 = (lane + 64 < M) ? cand[w][lane + 64] : SENT;
    int v3 = (lane + 96 < M) ? cand[w][lane + 96] : SENT;

    int r0 = 0, r1 = 0, r2 = 0, r3 = 0;
    {
        const int4* cp4 = reinterpret_cast<const int4*>(cand[w]);
        int nj4 = (M + 3) >> 2;
        if (M <= 64) {
            for (int j4 = 0; j4 < nj4; j4++) {
                int4 sv = cp4[j4];
                r0 += (sv.x < v0) + (sv.y < v0) + (sv.z < v0) + (sv.w < v0);
                r1 += (sv.x < v1) + (sv.y < v1) + (sv.z < v1) + (sv.w < v1);
            }
        } else {
            for (int j4 = 0; j4 < nj4; j4++) {
                int4 sv = cp4[j4];
                r0 += (sv.x < v0) + (sv.y < v0) + (sv.z < v0) + (sv.w < v0);
                r1 += (sv.x < v1) + (sv.y < v1) + (sv.z < v1) + (sv.w < v1);
                r2 += (sv.x < v2) + (sv.y < v2) + (sv.z < v2) + (sv.w < v2);
                r3 += (sv.x < v3) + (sv.y < v3) + (sv.z < v3) + (sv.w < v3);
            }
        }
    }
    __syncwarp();   // all reads of cand done before overwrite
    // scatter: sorted ascending, slot = rank (indices unique -> ranks unique).
    // SENT entries MUST NOT scatter (fast path leaves their rank at 0).
    if (v0 != SENT && r0 < NSAMP) cand[w][r0] = v0;
    if (v1 != SENT && r1 < NSAMP) cand[w][r1] = v1;
    if (v2 != SENT && r2 < NSAMP) cand[w][r2] = v2;
    if (v3 != SENT && r3 < NSAMP) cand[w][r3] = v3;
    __syncwarp();

    int cnt   = min(M, NSAMP);
    bool valid = lane < cnt;
    int first = (cnt > 0) ? cand[w][0] : 0;
    int id    = valid ? cand[w][lane] : first;
    float idn = (valid || cnt == 0) ? 1.0f : 0.0f;

    g_idx[q * NSAMP + lane] = id;             // coalesced, consumed by K5

    // ---- xyz part (3 channels), lane = sample slot ----
    float px = xyz[3 * id], py = xyz[3 * id + 1], pz = xyz[3 * id + 2];
    size_t ob = (((size_t)b * C_OUT) * NQ_P + (size_t)p) * NSAMP + (size_t)lane;
    const size_t st = (size_t)NQ_P * NSAMP;
    out[ob]          = __fsub_rn(px, qx);
    out[ob + st]     = __fsub_rn(py, qy);
    out[ob + 2 * st] = __fsub_rn(pz, qz);

    if (write_idn) {
        size_t nfe = (size_t)BATCH * C_OUT * NQ_P * NSAMP;
        out[nfe + (size_t)q * NSAMP + lane] = idn;
    }
}

// -------- K5: feature grouping, 4 warps per query (one per channel-quad) ----
#define GW_PB 8     // warps per block
__global__ __launch_bounds__(GW_PB * 32) void group_kernel(float* __restrict__ out) {
    __shared__ float4 sbuf[GW_PB][NSAMP * 4];      // 2KB per warp
    int w    = threadIdx.x >> 5;
    int lane = threadIdx.x & 31;
    int gw = blockIdx.x * GW_PB + w;
    int q  = gw >> 2;          // query
    int kk = gw & 3;           // channel-quad group: chunks [4kk, 4kk+4)
    int b = q >> 11;
    int p = q & (NQ_P - 1);

    int id = g_idx[q * NSAMP + lane];              // coalesced

    float4* mybuf = sbuf[w];
    int lc = lane & 3;                 // chunk within group
    int lr = lane >> 2;                // row base
    // stage chunks [4kk, 4kk+4) of all 32 sample rows
    #pragma unroll
    for (int t = 0; t < 4; t++) {
        int r = lr + 8 * t;
        int id_r = __shfl_sync(FULLM, id, r);
        float4 val = g_featT[(size_t)id_r * 16 + 4 * kk + lc];
        mybuf[r * 4 + (lc ^ (r & 3) ^ ((r >> 2) & 3))] = val;
    }
    __syncwarp();

    // drain transposed: lane = sample, 16 channels -> 16 coalesced stores
    size_t ob = (((size_t)b * C_OUT) * NQ_P + (size_t)p) * NSAMP + (size_t)lane;
    const size_t st = (size_t)NQ_P * NSAMP;
    size_t o = ob + 3 * st;
    int myswz = (lane & 3) ^ ((lane >> 2) & 3);
    #pragma unroll
    for (int j = 0; j < 4; j++) {
        float4 f = mybuf[lane * 4 + (j ^ myswz)];
        size_t oo = o + (size_t)(4 * (4 * kk + j)) * st;
        out[oo]          = f.x;
        out[oo + st]     = f.y;
        out[oo + 2 * st] = f.z;
        out[oo + 3 * st] = f.w;
    }
}

extern "C" void kernel_launch(void* const* d_in, const int* in_sizes, int n_in,
                              void* d_out, int out_size) {
    const float* xyz     = (const float*)d_in[0];   // (20000, 3)
    const float* new_xyz = (const float*)d_in[1];   // (2, 2048, 3)
    const float* feat    = (const float*)d_in[2];   // (64, 20000)
    float* out = (float*)d_out;

    long long nfe = (long long)BATCH * C_OUT * NQ_P * NSAMP;           // 18,350,080
    int write_idn = ((long long)out_size >= nfe + (long long)NQ * NSAMP) ? 1 : 0;

    // Fork: transpose (only needed by group_kernel) runs on a side stream,
    // overlapping the grid build + query chain on the main stream.
    cudaStream_t s2;
    cudaStreamCreateWithFlags(&s2, cudaStreamNonBlocking);
    cudaEvent_t e0, e1;
    cudaEventCreateWithFlags(&e0, cudaEventDisableTiming);
    cudaEventCreateWithFlags(&e1, cudaEventDisableTiming);

    cudaEventRecord(e0, 0);                 // fork point on capture stream
    cudaStreamWaitEvent(s2, e0, 0);
    transpose_kernel<<<T_BLOCKS, 256, 0, s2>>>(feat);
    cudaEventRecord(e1, s2);

    count_kernel<<<CNT_BLOCKS, 256>>>(xyz);
    scan_kernel<<<1, 1024>>>();
    scatter_kernel<<<CNT_BLOCKS, 256>>>(xyz);
    query_kernel<<<NQ / WPB, WPB * 32>>>(new_xyz, xyz, out, write_idn);

    cudaStreamWaitEvent(0, e1, 0);          // join: group needs featT
    group_kernel<<<(NQ * 4) / GW_PB, GW_PB * 32>>>(out);

    cudaEventDestroy(e0);
    cudaEventDestroy(e1);
    cudaStreamDestroy(s2);
}